// round 1
// baseline (speedup 1.0000x reference)
#include <cuda_runtime.h>
#include <math.h>

#define Bb   2
#define Nn   2048
#define Cc   1024
#define Hh   16
#define HDd  64
#define ROWS (Bb * Nn)          // 4096
#define LNEPS 1e-5f

// Scratch (device globals; no allocation allowed)
__device__ float g_q[Bb * Hh * Nn * HDd];
__device__ float g_k[Bb * Hh * Nn * HDd];
__device__ float g_v[Bb * Hh * Nn * HDd];
__device__ float g_o[Bb * Hh * Nn * HDd];

// ---------------------------------------------------------------------------
// Tiled GEMM: 64x64 tile, K-chunk 16, 256 threads, 4x4 microtile per thread
// ---------------------------------------------------------------------------
#define BM 64
#define BTN 64
#define BK 16

// QKV GEMM: [4096,1024] @ [1024,3072] + bias -> scatter into g_q/g_k/g_v
__global__ void qkv_gemm_kernel(const float* __restrict__ x,
                                const float* __restrict__ w,
                                const float* __restrict__ bias) {
    __shared__ float As[BK][BM + 1];
    __shared__ float Bs[BK][BTN + 1];
    const int tid  = threadIdx.x;
    const int row0 = (tid / 16) * 4;
    const int col0 = (tid % 16) * 4;
    const int gr   = blockIdx.y * BM;
    const int gc   = blockIdx.x * BTN;

    float acc[4][4] = {};
    for (int k0 = 0; k0 < Cc; k0 += BK) {
        #pragma unroll
        for (int i = 0; i < 4; i++) {
            int idx = tid + i * 256;
            int r = idx / BK, c = idx % BK;
            As[c][r] = x[(gr + r) * Cc + k0 + c];
        }
        #pragma unroll
        for (int i = 0; i < 4; i++) {
            int idx = tid + i * 256;
            int r = idx / BTN, c = idx % BTN;
            Bs[r][c] = w[(k0 + r) * (3 * Cc) + gc + c];
        }
        __syncthreads();
        #pragma unroll
        for (int kk = 0; kk < BK; kk++) {
            float a[4], b[4];
            #pragma unroll
            for (int i = 0; i < 4; i++) a[i] = As[kk][row0 + i];
            #pragma unroll
            for (int j = 0; j < 4; j++) b[j] = Bs[kk][col0 + j];
            #pragma unroll
            for (int i = 0; i < 4; i++)
                #pragma unroll
                for (int j = 0; j < 4; j++)
                    acc[i][j] += a[i] * b[j];
        }
        __syncthreads();
    }

    #pragma unroll
    for (int i = 0; i < 4; i++) {
        int row = gr + row0 + i;
        int b   = row / Nn;
        int n   = row % Nn;
        #pragma unroll
        for (int j = 0; j < 4; j++) {
            int col  = gc + col0 + j;
            float v  = acc[i][j] + bias[col];
            int which = col / Cc;
            int c    = col % Cc;
            int h    = c / HDd;
            int d    = c % HDd;
            int o    = ((b * Hh + h) * Nn + n) * HDd + d;
            if (which == 0)      g_q[o] = v;
            else if (which == 1) g_k[o] = v;
            else                 g_v[o] = v;
        }
    }
}

// ---------------------------------------------------------------------------
// LayerNorm over last dim (HD=64), one warp per row. Q rows also * HD^-0.5.
// ---------------------------------------------------------------------------
__global__ void ln_kernel(const float* __restrict__ gq, const float* __restrict__ beq,
                          const float* __restrict__ gk, const float* __restrict__ bek) {
    const int R = Bb * Hh * Nn;                       // 65536
    int warp = (blockIdx.x * blockDim.x + threadIdx.x) >> 5;
    int lane = threadIdx.x & 31;
    if (warp >= 2 * R) return;

    bool isq = warp < R;
    float* buf        = isq ? g_q : g_k;
    const float* gam  = isq ? gq  : gk;
    const float* bet  = isq ? beq : bek;
    float scale       = isq ? 0.125f : 1.0f;          // HD^-0.5 = 1/8
    int row = isq ? warp : warp - R;

    float v0 = buf[row * HDd + lane];
    float v1 = buf[row * HDd + 32 + lane];
    float s  = v0 + v1;
    float ss = v0 * v0 + v1 * v1;
    #pragma unroll
    for (int off = 16; off; off >>= 1) {
        s  += __shfl_xor_sync(0xffffffffu, s,  off);
        ss += __shfl_xor_sync(0xffffffffu, ss, off);
    }
    float mu  = s * (1.0f / HDd);
    float var = ss * (1.0f / HDd) - mu * mu;
    float inv = rsqrtf(var + LNEPS);
    buf[row * HDd + lane]      = ((v0 - mu) * inv * gam[lane]      + bet[lane])      * scale;
    buf[row * HDd + 32 + lane] = ((v1 - mu) * inv * gam[lane + 32] + bet[lane + 32]) * scale;
}

// ---------------------------------------------------------------------------
// Flash attention: per (b,h), 64 q-rows per CTA, KV tiles of 64.
// 256 threads = 64 rows x 4 col-groups of 16.
// ---------------------------------------------------------------------------
#define ATTN_SMEM (4 * 64 * 65 * 4)   // Qs,Ks,Vs,Ps each [64][65] f32 = 66560 B

__global__ void attn_kernel() {
    extern __shared__ float sm[];
    float (*Qs)[65] = (float (*)[65])(sm);
    float (*Ks)[65] = (float (*)[65])(sm + 64 * 65);
    float (*Vs)[65] = (float (*)[65])(sm + 2 * 64 * 65);
    float (*Ps)[65] = (float (*)[65])(sm + 3 * 64 * 65);

    const int tid = threadIdx.x;
    const int r   = tid >> 2;           // q row within tile (0..63)
    const int cq  = tid & 3;            // col-group (0..3), 16 cols each
    const int bh  = blockIdx.y;         // b*H + h (0..31)
    const int q0  = blockIdx.x * 64;

    const float* Qg = g_q + (bh * Nn + q0) * HDd;
    // load Q tile
    #pragma unroll
    for (int i = 0; i < 16; i++) {
        int idx = tid + i * 256;
        Qs[idx / 64][idx % 64] = Qg[idx];
    }

    float m = -INFINITY, l = 0.0f;
    float o[16];
    #pragma unroll
    for (int i = 0; i < 16; i++) o[i] = 0.0f;

    for (int kt = 0; kt < Nn / 64; kt++) {
        const float* Kg = g_k + (bh * Nn + kt * 64) * HDd;
        const float* Vg = g_v + (bh * Nn + kt * 64) * HDd;
        __syncthreads();
        #pragma unroll
        for (int i = 0; i < 16; i++) {
            int idx = tid + i * 256;
            Ks[idx / 64][idx % 64] = Kg[idx];
            Vs[idx / 64][idx % 64] = Vg[idx];
        }
        __syncthreads();

        // S[r][cq*16 + j] = Q[r] . K[c]
        float s[16];
        #pragma unroll
        for (int j = 0; j < 16; j++) s[j] = 0.0f;
        #pragma unroll 4
        for (int d = 0; d < HDd; d++) {
            float qd = Qs[r][d];
            #pragma unroll
            for (int j = 0; j < 16; j++)
                s[j] += qd * Ks[cq * 16 + j][d];
        }

        // online softmax
        float tmax = s[0];
        #pragma unroll
        for (int j = 1; j < 16; j++) tmax = fmaxf(tmax, s[j]);
        tmax = fmaxf(tmax, __shfl_xor_sync(0xffffffffu, tmax, 1));
        tmax = fmaxf(tmax, __shfl_xor_sync(0xffffffffu, tmax, 2));
        float mnew = fmaxf(m, tmax);
        float corr = __expf(m - mnew);
        float tsum = 0.0f;
        #pragma unroll
        for (int j = 0; j < 16; j++) {
            s[j] = __expf(s[j] - mnew);
            tsum += s[j];
        }
        tsum += __shfl_xor_sync(0xffffffffu, tsum, 1);
        tsum += __shfl_xor_sync(0xffffffffu, tsum, 2);
        l = l * corr + tsum;
        m = mnew;
        #pragma unroll
        for (int i = 0; i < 16; i++) o[i] *= corr;

        #pragma unroll
        for (int j = 0; j < 16; j++) Ps[r][cq * 16 + j] = s[j];
        __syncthreads();

        // O[r][cq*16+dd] += sum_j P[r][j] * V[j][cq*16+dd]
        #pragma unroll 4
        for (int j = 0; j < 64; j++) {
            float pv = Ps[r][j];
            #pragma unroll
            for (int dd = 0; dd < 16; dd++)
                o[dd] += pv * Vs[j][cq * 16 + dd];
        }
    }

    float linv = 1.0f / l;
    float* Og = g_o + (bh * Nn + q0 + r) * HDd + cq * 16;
    #pragma unroll
    for (int dd = 0; dd < 16; dd++) Og[dd] = o[dd] * linv;
}

// ---------------------------------------------------------------------------
// Projection GEMM: A gathered from g_o head-major layout, [4096,1024]@[1024,1024]
// ---------------------------------------------------------------------------
__global__ void proj_gemm_kernel(const float* __restrict__ w,
                                 const float* __restrict__ bias,
                                 float* __restrict__ out) {
    __shared__ float As[BK][BM + 1];
    __shared__ float Bs[BK][BTN + 1];
    const int tid  = threadIdx.x;
    const int row0 = (tid / 16) * 4;
    const int col0 = (tid % 16) * 4;
    const int gr   = blockIdx.y * BM;
    const int gc   = blockIdx.x * BTN;

    float acc[4][4] = {};
    for (int k0 = 0; k0 < Cc; k0 += BK) {
        #pragma unroll
        for (int i = 0; i < 4; i++) {
            int idx = tid + i * 256;
            int r = idx / BK, c = idx % BK;
            int row = gr + r;
            int b = row / Nn, n = row % Nn;
            int k = k0 + c;
            int h = k / HDd, d = k % HDd;
            As[c][r] = g_o[((b * Hh + h) * Nn + n) * HDd + d];
        }
        #pragma unroll
        for (int i = 0; i < 4; i++) {
            int idx = tid + i * 256;
            int r = idx / BTN, c = idx % BTN;
            Bs[r][c] = w[(k0 + r) * Cc + gc + c];
        }
        __syncthreads();
        #pragma unroll
        for (int kk = 0; kk < BK; kk++) {
            float a[4], b[4];
            #pragma unroll
            for (int i = 0; i < 4; i++) a[i] = As[kk][row0 + i];
            #pragma unroll
            for (int j = 0; j < 4; j++) b[j] = Bs[kk][col0 + j];
            #pragma unroll
            for (int i = 0; i < 4; i++)
                #pragma unroll
                for (int j = 0; j < 4; j++)
                    acc[i][j] += a[i] * b[j];
        }
        __syncthreads();
    }

    #pragma unroll
    for (int i = 0; i < 4; i++) {
        int row = gr + row0 + i;
        #pragma unroll
        for (int j = 0; j < 4; j++) {
            int col = gc + col0 + j;
            out[row * Cc + col] = acc[i][j] + bias[col];
        }
    }
}

// ---------------------------------------------------------------------------
extern "C" void kernel_launch(void* const* d_in, const int* in_sizes, int n_in,
                              void* d_out, int out_size) {
    const float* x      = (const float*)d_in[0];
    const float* w_qkv  = (const float*)d_in[1];
    const float* b_qkv  = (const float*)d_in[2];
    const float* gq     = (const float*)d_in[3];
    const float* beq    = (const float*)d_in[4];
    const float* gk     = (const float*)d_in[5];
    const float* bek    = (const float*)d_in[6];
    const float* w_proj = (const float*)d_in[7];
    const float* b_proj = (const float*)d_in[8];
    float* out = (float*)d_out;

    cudaFuncSetAttribute(attn_kernel, cudaFuncAttributeMaxDynamicSharedMemorySize, ATTN_SMEM);

    // 1) QKV GEMM + scatter
    qkv_gemm_kernel<<<dim3(3 * Cc / BTN, ROWS / BM), 256>>>(x, w_qkv, b_qkv);
    // 2) LN on Q (with scale) and K
    {
        int warps = 2 * Bb * Hh * Nn;           // 131072
        ln_kernel<<<warps / 8, 256>>>(gq, beq, gk, bek);
    }
    // 3) attention
    attn_kernel<<<dim3(Nn / 64, Bb * Hh), 256, ATTN_SMEM>>>();
    // 4) projection
    proj_gemm_kernel<<<dim3(Cc / BTN, ROWS / BM), 256>>>(w_proj, b_proj, out);
}

// round 7
// speedup vs baseline: 2.7491x; 2.7491x over previous
#include <cuda_runtime.h>
#include <math.h>

#define Bb   2
#define Nn   2048
#define Cc   1024
#define Hh   16
#define HDd  64
#define ROWS (Bb * Nn)          // 4096
#define LNEPS 1e-5f

// Scratch (device globals; allocation is forbidden). All N-MAJOR [bh][n][d].
__device__ float g_q[Bb * Hh * Nn * HDd];
__device__ float g_k[Bb * Hh * Nn * HDd];
__device__ float g_v[Bb * Hh * Nn * HDd];
__device__ float g_o[Bb * Hh * Nn * HDd];

// ---------------------------------------------------------------------------
// QKV GEMM: [4096,1024] @ [1024,3072] + bias -> scatter g_q/g_k/g_v (n-major)
// 128x128 tile, BK=16, 256 threads (16x16), 8x8 microtile.
// ---------------------------------------------------------------------------
#define GS 132   // smem row stride (floats), multiple of 4

__global__ void qkv_gemm_kernel(const float* __restrict__ x,
                                const float* __restrict__ w,
                                const float* __restrict__ bias) {
    __shared__ float As[16 * GS];   // [k][m] (transposed A tile)
    __shared__ float Bs[16 * GS];   // [k][n]

    const int tid = threadIdx.x;
    const int r0  = (tid >> 4) * 8;
    const int c0  = (tid & 15) * 8;
    const int gr  = blockIdx.y * 128;
    const int gc  = blockIdx.x * 128;

    float acc[8][8];
    #pragma unroll
    for (int i = 0; i < 8; i++)
        #pragma unroll
        for (int j = 0; j < 8; j++) acc[i][j] = 0.0f;

    for (int k0 = 0; k0 < Cc; k0 += 16) {
        #pragma unroll
        for (int i = 0; i < 8; i++) {
            int idx = tid + i * 256;           // 0..2047
            int m = idx >> 4, k = idx & 15;
            As[k * GS + m] = x[(size_t)(gr + m) * Cc + k0 + k];
        }
        #pragma unroll
        for (int p = 0; p < 2; p++) {
            int idx = tid + p * 256;           // 0..511 float4s
            int k = idx >> 5, n4 = idx & 31;
            *(float4*)&Bs[k * GS + n4 * 4] =
                *(const float4*)(w + (size_t)(k0 + k) * (3 * Cc) + gc + n4 * 4);
        }
        __syncthreads();

        #pragma unroll
        for (int kk = 0; kk < 16; kk++) {
            float4 a0 = *(float4*)&As[kk * GS + r0];
            float4 a1 = *(float4*)&As[kk * GS + r0 + 4];
            float4 b0 = *(float4*)&Bs[kk * GS + c0];
            float4 b1 = *(float4*)&Bs[kk * GS + c0 + 4];
            float a[8] = {a0.x, a0.y, a0.z, a0.w, a1.x, a1.y, a1.z, a1.w};
            float b[8] = {b0.x, b0.y, b0.z, b0.w, b1.x, b1.y, b1.z, b1.w};
            #pragma unroll
            for (int i = 0; i < 8; i++)
                #pragma unroll
                for (int j = 0; j < 8; j++) acc[i][j] += a[i] * b[j];
        }
        __syncthreads();
    }

    #pragma unroll
    for (int i = 0; i < 8; i++) {
        int row = gr + r0 + i;
        int b = row / Nn, n = row % Nn;
        #pragma unroll
        for (int j = 0; j < 8; j++) {
            int col = gc + c0 + j;
            float v = acc[i][j] + bias[col];
            int wh = col >> 10;
            int ci = col & 1023;
            int h  = ci >> 6, d = ci & 63;
            size_t o = ((size_t)(b * Hh + h) * Nn + n) * HDd + d;
            if (wh == 0)      g_q[o] = v;
            else if (wh == 1) g_k[o] = v;
            else              g_v[o] = v;
        }
    }
}

// ---------------------------------------------------------------------------
// LayerNorm over HD=64, one warp per row (exact R0 kernel).
// ---------------------------------------------------------------------------
__global__ void ln_kernel(const float* __restrict__ gq, const float* __restrict__ beq,
                          const float* __restrict__ gk, const float* __restrict__ bek) {
    const int R = Bb * Hh * Nn;
    int warp = (blockIdx.x * blockDim.x + threadIdx.x) >> 5;
    int lane = threadIdx.x & 31;
    if (warp >= 2 * R) return;

    bool isq = warp < R;
    float* buf       = isq ? g_q : g_k;
    const float* gam = isq ? gq  : gk;
    const float* bet = isq ? beq : bek;
    float scale      = isq ? 0.125f : 1.0f;
    int row = isq ? warp : warp - R;

    float v0 = buf[row * HDd + lane];
    float v1 = buf[row * HDd + 32 + lane];
    float s  = v0 + v1;
    float ss = v0 * v0 + v1 * v1;
    #pragma unroll
    for (int off = 16; off; off >>= 1) {
        s  += __shfl_xor_sync(0xffffffffu, s,  off);
        ss += __shfl_xor_sync(0xffffffffu, ss, off);
    }
    float mu  = s * (1.0f / HDd);
    float var = ss * (1.0f / HDd) - mu * mu;
    float inv = rsqrtf(var + LNEPS);
    buf[row * HDd + lane]      = ((v0 - mu) * inv * gam[lane]      + bet[lane])      * scale;
    buf[row * HDd + 32 + lane] = ((v1 - mu) * inv * gam[lane + 32] + bet[lane + 32]) * scale;
}

// ---------------------------------------------------------------------------
// Flash attention: per (b,h), Q-block 128, KV tiles 128, 256 threads (16x16).
// S stage : thread owns 8 q-rows x 8 keys  (c0s = (tid&15)*8, 128 keys)
// PV stage: thread owns 8 q-rows x 4 d     (c0d = (tid&15)*4, 64 d)
// ---------------------------------------------------------------------------
#define VS_  68    // Qs/Vs stride (floats)
#define KTS 132    // Kt stride
#define PS_ 132    // Ps stride (128 keys per row)
#define ATTN_SMEM ((128 * VS_ + 64 * KTS + 128 * VS_ + 128 * PS_) * 4)   // 171008 B

__global__ void attn_kernel() {
    extern __shared__ float sm[];
    float* Qs = sm;                                   // [q=128][d=64]   stride VS_
    float* Kt = Qs + 128 * VS_;                       // [d=64][key=128] stride KTS
    float* Vs = Kt + 64 * KTS;                        // [key=128][d=64] stride VS_
    float* Ps = Vs + 128 * VS_;                       // [q=128][key=128] stride PS_

    const int tid = threadIdx.x;
    const int r0  = (tid >> 4) * 8;
    const int c0s = (tid & 15) * 8;   // key group for S
    const int c0d = (tid & 15) * 4;   // d group for PV/O
    const int bh  = blockIdx.y;
    const int q0  = blockIdx.x * 128;

    const float* Qg = g_q + ((size_t)bh * Nn + q0) * HDd;
    #pragma unroll
    for (int i = 0; i < 8; i++) {
        int idx = tid + i * 256;          // 0..2047 float4s
        int row = idx >> 4, d4 = idx & 15;
        *(float4*)&Qs[row * VS_ + d4 * 4] = *(const float4*)(Qg + (size_t)row * HDd + d4 * 4);
    }

    float o[8][4];
    float m[8], l[8];
    #pragma unroll
    for (int i = 0; i < 8; i++) {
        m[i] = -INFINITY; l[i] = 0.0f;
        #pragma unroll
        for (int j = 0; j < 4; j++) o[i][j] = 0.0f;
    }

    for (int kt = 0; kt < Nn / 128; kt++) {
        __syncthreads();                  // prior-iter readers done before overwrite
        const float* Kg = g_k + ((size_t)bh * Nn + kt * 128) * HDd;
        const float* Vg = g_v + ((size_t)bh * Nn + kt * 128) * HDd;
        #pragma unroll
        for (int i = 0; i < 32; i++) {
            int idx = tid + i * 256;      // 0..8191
            int key = idx >> 6, d = idx & 63;
            Kt[d * KTS + key] = Kg[(size_t)key * HDd + d];
        }
        #pragma unroll
        for (int i = 0; i < 8; i++) {
            int idx = tid + i * 256;      // 0..2047 float4s
            int row = idx >> 4, d4 = idx & 15;
            *(float4*)&Vs[row * VS_ + d4 * 4] = *(const float4*)(Vg + (size_t)row * HDd + d4 * 4);
        }
        __syncthreads();

        // ---- S = Q . K^T : 8 q-rows x 8 keys, sum over 64 d ----
        float s[8][8];
        #pragma unroll
        for (int i = 0; i < 8; i++)
            #pragma unroll
            for (int j = 0; j < 8; j++) s[i][j] = 0.0f;

        #pragma unroll 4
        for (int d = 0; d < HDd; d++) {
            float a[8];
            #pragma unroll
            for (int i = 0; i < 8; i++) a[i] = Qs[(r0 + i) * VS_ + d];
            float4 b0 = *(float4*)&Kt[d * KTS + c0s];
            float4 b1 = *(float4*)&Kt[d * KTS + c0s + 4];
            float b[8] = {b0.x, b0.y, b0.z, b0.w, b1.x, b1.y, b1.z, b1.w};
            #pragma unroll
            for (int i = 0; i < 8; i++)
                #pragma unroll
                for (int j = 0; j < 8; j++) s[i][j] += a[i] * b[j];
        }

        // ---- online softmax: rows r0..r0+7 reduced across the 16 key-lanes ----
        #pragma unroll
        for (int i = 0; i < 8; i++) {
            float mx = s[i][0];
            #pragma unroll
            for (int j = 1; j < 8; j++) mx = fmaxf(mx, s[i][j]);
            mx = fmaxf(mx, __shfl_xor_sync(0xffffffffu, mx, 1));
            mx = fmaxf(mx, __shfl_xor_sync(0xffffffffu, mx, 2));
            mx = fmaxf(mx, __shfl_xor_sync(0xffffffffu, mx, 4));
            mx = fmaxf(mx, __shfl_xor_sync(0xffffffffu, mx, 8));
            float mn   = fmaxf(m[i], mx);
            float corr = __expf(m[i] - mn);
            float sum  = 0.0f;
            #pragma unroll
            for (int j = 0; j < 8; j++) {
                s[i][j] = __expf(s[i][j] - mn);
                sum += s[i][j];
            }
            sum += __shfl_xor_sync(0xffffffffu, sum, 1);
            sum += __shfl_xor_sync(0xffffffffu, sum, 2);
            sum += __shfl_xor_sync(0xffffffffu, sum, 4);
            sum += __shfl_xor_sync(0xffffffffu, sum, 8);
            l[i] = l[i] * corr + sum;
            m[i] = mn;
            #pragma unroll
            for (int j = 0; j < 4; j++) o[i][j] *= corr;
        }

        // write P (float4 x2 per row)
        #pragma unroll
        for (int i = 0; i < 8; i++) {
            *(float4*)&Ps[(r0 + i) * PS_ + c0s]     = make_float4(s[i][0], s[i][1], s[i][2], s[i][3]);
            *(float4*)&Ps[(r0 + i) * PS_ + c0s + 4] = make_float4(s[i][4], s[i][5], s[i][6], s[i][7]);
        }
        __syncthreads();

        // ---- O += P . V : 8 q-rows x 4 d, sum over 128 keys ----
        #pragma unroll 4
        for (int k = 0; k < 128; k++) {
            float p[8];
            #pragma unroll
            for (int i = 0; i < 8; i++) p[i] = Ps[(r0 + i) * PS_ + k];   // broadcast
            float4 vv = *(float4*)&Vs[k * VS_ + c0d];
            float v[4] = {vv.x, vv.y, vv.z, vv.w};
            #pragma unroll
            for (int i = 0; i < 8; i++)
                #pragma unroll
                for (int j = 0; j < 4; j++) o[i][j] += p[i] * v[j];
        }
    }

    // normalize + write O (n-major)
    float* Og = g_o + ((size_t)bh * Nn + q0) * HDd;
    #pragma unroll
    for (int i = 0; i < 8; i++) {
        float inv = 1.0f / l[i];
        *(float4*)(Og + (size_t)(r0 + i) * HDd + c0d) =
            make_float4(o[i][0] * inv, o[i][1] * inv, o[i][2] * inv, o[i][3] * inv);
    }
}

// ---------------------------------------------------------------------------
// Projection GEMM: A gathered in-staging from g_o (n-major), + bias -> out
// ---------------------------------------------------------------------------
__global__ void proj_gemm_kernel(const float* __restrict__ w,
                                 const float* __restrict__ bias,
                                 float* __restrict__ out) {
    __shared__ float As[16 * GS];
    __shared__ float Bs[16 * GS];

    const int tid = threadIdx.x;
    const int r0  = (tid >> 4) * 8;
    const int c0  = (tid & 15) * 8;
    const int gr  = blockIdx.y * 128;
    const int gc  = blockIdx.x * 128;

    float acc[8][8];
    #pragma unroll
    for (int i = 0; i < 8; i++)
        #pragma unroll
        for (int j = 0; j < 8; j++) acc[i][j] = 0.0f;

    for (int k0 = 0; k0 < Cc; k0 += 16) {
        #pragma unroll
        for (int i = 0; i < 8; i++) {
            int idx = tid + i * 256;
            int mm = idx >> 4, k = idx & 15;
            int row = gr + mm;
            int b = row / Nn, n = row % Nn;
            int kg = k0 + k;
            int h = kg >> 6, d = kg & 63;
            As[k * GS + mm] = g_o[((size_t)(b * Hh + h) * Nn + n) * HDd + d];
        }
        #pragma unroll
        for (int p = 0; p < 2; p++) {
            int idx = tid + p * 256;
            int k = idx >> 5, n4 = idx & 31;
            *(float4*)&Bs[k * GS + n4 * 4] =
                *(const float4*)(w + (size_t)(k0 + k) * Cc + gc + n4 * 4);
        }
        __syncthreads();

        #pragma unroll
        for (int kk = 0; kk < 16; kk++) {
            float4 a0 = *(float4*)&As[kk * GS + r0];
            float4 a1 = *(float4*)&As[kk * GS + r0 + 4];
            float4 b0 = *(float4*)&Bs[kk * GS + c0];
            float4 b1 = *(float4*)&Bs[kk * GS + c0 + 4];
            float a[8] = {a0.x, a0.y, a0.z, a0.w, a1.x, a1.y, a1.z, a1.w};
            float b[8] = {b0.x, b0.y, b0.z, b0.w, b1.x, b1.y, b1.z, b1.w};
            #pragma unroll
            for (int i = 0; i < 8; i++)
                #pragma unroll
                for (int j = 0; j < 8; j++) acc[i][j] += a[i] * b[j];
        }
        __syncthreads();
    }

    #pragma unroll
    for (int i = 0; i < 8; i++) {
        int row = gr + r0 + i;
        float4 w0 = make_float4(acc[i][0] + bias[gc + c0 + 0], acc[i][1] + bias[gc + c0 + 1],
                                acc[i][2] + bias[gc + c0 + 2], acc[i][3] + bias[gc + c0 + 3]);
        float4 w1 = make_float4(acc[i][4] + bias[gc + c0 + 4], acc[i][5] + bias[gc + c0 + 5],
                                acc[i][6] + bias[gc + c0 + 6], acc[i][7] + bias[gc + c0 + 7]);
        *(float4*)(out + (size_t)row * Cc + gc + c0)     = w0;
        *(float4*)(out + (size_t)row * Cc + gc + c0 + 4) = w1;
    }
}

// ---------------------------------------------------------------------------
extern "C" void kernel_launch(void* const* d_in, const int* in_sizes, int n_in,
                              void* d_out, int out_size) {
    const float* x      = (const float*)d_in[0];
    const float* w_qkv  = (const float*)d_in[1];
    const float* b_qkv  = (const float*)d_in[2];
    const float* gq     = (const float*)d_in[3];
    const float* beq    = (const float*)d_in[4];
    const float* gk     = (const float*)d_in[5];
    const float* bek    = (const float*)d_in[6];
    const float* w_proj = (const float*)d_in[7];
    const float* b_proj = (const float*)d_in[8];
    float* out = (float*)d_out;

    cudaFuncSetAttribute(attn_kernel, cudaFuncAttributeMaxDynamicSharedMemorySize, ATTN_SMEM);

    qkv_gemm_kernel<<<dim3(3 * Cc / 128, ROWS / 128), 256>>>(x, w_qkv, b_qkv);
    ln_kernel<<<(2 * Bb * Hh * Nn) / 8, 256>>>(gq, beq, gk, bek);
    attn_kernel<<<dim3(Nn / 128, Bb * Hh), 256, ATTN_SMEM>>>();
    proj_gemm_kernel<<<dim3(Cc / 128, ROWS / 128), 256>>>(w_proj, b_proj, out);
}

// round 8
// speedup vs baseline: 2.9930x; 1.0887x over previous
#include <cuda_runtime.h>
#include <cuda_bf16.h>
#include <mma.h>
#include <math.h>

using namespace nvcuda;

#define Bb   2
#define Nn   2048
#define Cc   1024
#define Hh   16
#define HDd  64
#define ROWS (Bb * Nn)          // 4096
#define LNEPS 1e-5f

typedef __nv_bfloat16 bf16;

// Scratch (device globals; allocation is forbidden). All N-MAJOR [bh][n][d].
__device__ float g_q[Bb * Hh * Nn * HDd];
__device__ float g_k[Bb * Hh * Nn * HDd];
__device__ float g_v[Bb * Hh * Nn * HDd];
__device__ float g_o[Bb * Hh * Nn * HDd];

__device__ __forceinline__ void split_bf16(float f, bf16& hi, bf16& lo) {
    hi = __float2bfloat16(f);
    lo = __float2bfloat16(f - __bfloat162float(hi));
}

// ---------------------------------------------------------------------------
// bf16 hi/lo wmma GEMM (non-templated). 128x128 tile, BK=16, 256 threads,
// 8 warps (2x4), warp tile 64x32 = 4x2 m16n16k16 frags, 3 MMAs each (hi/lo).
// mode=1: A=x, epilogue scatters qkv.  mode=0: A gathered from g_o, out+bias.
// ---------------------------------------------------------------------------
#define ALD 24     // A smem stride (bf16): 48B, mult of 16B
#define BLD 136    // B smem stride (bf16): 272B
#define SLD 20     // staging stride (f32): 80B

// shared pool partition (float4 units, offsets even -> 32B aligned)
#define OFF_ASH 0
#define OFF_ASL 384                  // 128*24*2/16
#define OFF_BSH 768
#define OFF_BSL 1040                 // +16*136*2/16 = 272
#define OFF_ST  1312
#define POOL_SZ 1952                 // +8*16*20*4/16 = 640

__global__ void gemm_wmma(const float* __restrict__ A,
                          const float* __restrict__ W,
                          const float* __restrict__ bias,
                          float* __restrict__ out,
                          int ldw, int mode) {
    __shared__ float4 pool[POOL_SZ];
    bf16*  Ash = (bf16*)(pool + OFF_ASH);
    bf16*  Asl = (bf16*)(pool + OFF_ASL);
    bf16*  Bsh = (bf16*)(pool + OFF_BSH);
    bf16*  Bsl = (bf16*)(pool + OFF_BSL);
    float* St  = (float*)(pool + OFF_ST);

    const int tid   = threadIdx.x;
    const int wid   = tid >> 5;
    const int lane  = tid & 31;
    const int warpM = wid >> 2;           // 0..1 -> 64-row band
    const int warpN = wid & 3;            // 0..3 -> 32-col band
    const int gr    = blockIdx.y * 128;
    const int gc    = blockIdx.x * 128;

    wmma::fragment<wmma::accumulator, 16, 16, 16, float> cf[4][2];
    #pragma unroll
    for (int mt = 0; mt < 4; mt++)
        #pragma unroll
        for (int nt = 0; nt < 2; nt++) wmma::fill_fragment(cf[mt][nt], 0.0f);

    for (int k0 = 0; k0 < Cc; k0 += 16) {
        // stage A 128x16 -> hi/lo
        if (mode) {
            #pragma unroll
            for (int p = 0; p < 2; p++) {
                int idx = tid + p * 256;       // 0..511 float4s
                int c4  = idx & 3;
                int mm  = idx >> 2;
                float4 v = *(const float4*)(A + (size_t)(gr + mm) * Cc + k0 + c4 * 4);
                bf16 h, l;
                split_bf16(v.x, h, l); Ash[mm * ALD + c4 * 4 + 0] = h; Asl[mm * ALD + c4 * 4 + 0] = l;
                split_bf16(v.y, h, l); Ash[mm * ALD + c4 * 4 + 1] = h; Asl[mm * ALD + c4 * 4 + 1] = l;
                split_bf16(v.z, h, l); Ash[mm * ALD + c4 * 4 + 2] = h; Asl[mm * ALD + c4 * 4 + 2] = l;
                split_bf16(v.w, h, l); Ash[mm * ALD + c4 * 4 + 3] = h; Asl[mm * ALD + c4 * 4 + 3] = l;
            }
        } else {
            #pragma unroll
            for (int i = 0; i < 8; i++) {
                int idx = tid + i * 256;       // 0..2047 scalars
                int mm = idx >> 4, k = idx & 15;
                int row = gr + mm;
                int b = row / Nn, n = row % Nn;
                int kg = k0 + k;
                int h = kg >> 6, d = kg & 63;
                float v = g_o[((size_t)(b * Hh + h) * Nn + n) * HDd + d];
                bf16 hh, ll;
                split_bf16(v, hh, ll);
                Ash[mm * ALD + k] = hh;
                Asl[mm * ALD + k] = ll;
            }
        }
        // stage B 16x128 -> hi/lo
        #pragma unroll
        for (int p = 0; p < 2; p++) {
            int idx = tid + p * 256;           // 0..511 float4s
            int k  = idx >> 5;
            int n4 = idx & 31;
            float4 v = *(const float4*)(W + (size_t)(k0 + k) * ldw + gc + n4 * 4);
            bf16 h, l;
            split_bf16(v.x, h, l); Bsh[k * BLD + n4 * 4 + 0] = h; Bsl[k * BLD + n4 * 4 + 0] = l;
            split_bf16(v.y, h, l); Bsh[k * BLD + n4 * 4 + 1] = h; Bsl[k * BLD + n4 * 4 + 1] = l;
            split_bf16(v.z, h, l); Bsh[k * BLD + n4 * 4 + 2] = h; Bsl[k * BLD + n4 * 4 + 2] = l;
            split_bf16(v.w, h, l); Bsh[k * BLD + n4 * 4 + 3] = h; Bsl[k * BLD + n4 * 4 + 3] = l;
        }
        __syncthreads();

        wmma::fragment<wmma::matrix_a, 16, 16, 16, bf16, wmma::row_major> ah[4], al[4];
        wmma::fragment<wmma::matrix_b, 16, 16, 16, bf16, wmma::row_major> bh[2], bl[2];
        #pragma unroll
        for (int mt = 0; mt < 4; mt++) {
            wmma::load_matrix_sync(ah[mt], &Ash[(warpM * 64 + mt * 16) * ALD], ALD);
            wmma::load_matrix_sync(al[mt], &Asl[(warpM * 64 + mt * 16) * ALD], ALD);
        }
        #pragma unroll
        for (int nt = 0; nt < 2; nt++) {
            wmma::load_matrix_sync(bh[nt], &Bsh[warpN * 32 + nt * 16], BLD);
            wmma::load_matrix_sync(bl[nt], &Bsl[warpN * 32 + nt * 16], BLD);
        }
        #pragma unroll
        for (int mt = 0; mt < 4; mt++)
            #pragma unroll
            for (int nt = 0; nt < 2; nt++) {
                wmma::mma_sync(cf[mt][nt], ah[mt], bh[nt], cf[mt][nt]);
                wmma::mma_sync(cf[mt][nt], ah[mt], bl[nt], cf[mt][nt]);
                wmma::mma_sync(cf[mt][nt], al[mt], bh[nt], cf[mt][nt]);
            }
        __syncthreads();
    }

    // epilogue: stage 16x16 fragments through smem, add bias, write/scatter
    float* stg = &St[wid * 16 * SLD];
    #pragma unroll
    for (int mt = 0; mt < 4; mt++) {
        #pragma unroll
        for (int nt = 0; nt < 2; nt++) {
            wmma::store_matrix_sync(stg, cf[mt][nt], SLD, wmma::mem_row_major);
            __syncwarp();
            #pragma unroll
            for (int i = 0; i < 8; i++) {
                int e = lane * 8 + i;
                int r = e >> 4, c = e & 15;
                int row = gr + warpM * 64 + mt * 16 + r;
                int col = gc + warpN * 32 + nt * 16 + c;
                float v = stg[r * SLD + c] + bias[col];
                if (mode) {
                    int b  = row / Nn, n = row % Nn;
                    int wh = col >> 10;
                    int ci = col & 1023;
                    int h  = ci >> 6, d = ci & 63;
                    size_t o = ((size_t)(b * Hh + h) * Nn + n) * HDd + d;
                    if (wh == 0)      g_q[o] = v;
                    else if (wh == 1) g_k[o] = v;
                    else              g_v[o] = v;
                } else {
                    out[(size_t)row * Cc + col] = v;
                }
            }
            __syncwarp();
        }
    }
}

// ---------------------------------------------------------------------------
// LayerNorm over HD=64, one warp per row (unchanged, proven).
// ---------------------------------------------------------------------------
__global__ void ln_kernel(const float* __restrict__ gq, const float* __restrict__ beq,
                          const float* __restrict__ gk, const float* __restrict__ bek) {
    const int R = Bb * Hh * Nn;
    int warp = (blockIdx.x * blockDim.x + threadIdx.x) >> 5;
    int lane = threadIdx.x & 31;
    if (warp >= 2 * R) return;

    bool isq = warp < R;
    float* buf       = isq ? g_q : g_k;
    const float* gam = isq ? gq  : gk;
    const float* bet = isq ? beq : bek;
    float scale      = isq ? 0.125f : 1.0f;
    int row = isq ? warp : warp - R;

    float v0 = buf[row * HDd + lane];
    float v1 = buf[row * HDd + 32 + lane];
    float s  = v0 + v1;
    float ss = v0 * v0 + v1 * v1;
    #pragma unroll
    for (int off = 16; off; off >>= 1) {
        s  += __shfl_xor_sync(0xffffffffu, s,  off);
        ss += __shfl_xor_sync(0xffffffffu, ss, off);
    }
    float mu  = s * (1.0f / HDd);
    float var = ss * (1.0f / HDd) - mu * mu;
    float inv = rsqrtf(var + LNEPS);
    buf[row * HDd + lane]      = ((v0 - mu) * inv * gam[lane]      + bet[lane])      * scale;
    buf[row * HDd + 32 + lane] = ((v1 - mu) * inv * gam[lane + 32] + bet[lane + 32]) * scale;
}

// ---------------------------------------------------------------------------
// Flash attention (unchanged from R7, proven).
// ---------------------------------------------------------------------------
#define VS_  68
#define KTS 132
#define PS_ 132
#define ATTN_SMEM ((128 * VS_ + 64 * KTS + 128 * VS_ + 128 * PS_) * 4)   // 171008 B

__global__ void attn_kernel() {
    extern __shared__ float sm[];
    float* Qs = sm;
    float* Kt = Qs + 128 * VS_;
    float* Vs = Kt + 64 * KTS;
    float* Ps = Vs + 128 * VS_;

    const int tid = threadIdx.x;
    const int r0  = (tid >> 4) * 8;
    const int c0s = (tid & 15) * 8;
    const int c0d = (tid & 15) * 4;
    const int bh  = blockIdx.y;
    const int q0  = blockIdx.x * 128;

    const float* Qg = g_q + ((size_t)bh * Nn + q0) * HDd;
    #pragma unroll
    for (int i = 0; i < 8; i++) {
        int idx = tid + i * 256;
        int row = idx >> 4, d4 = idx & 15;
        *(float4*)&Qs[row * VS_ + d4 * 4] = *(const float4*)(Qg + (size_t)row * HDd + d4 * 4);
    }

    float o[8][4];
    float m[8], l[8];
    #pragma unroll
    for (int i = 0; i < 8; i++) {
        m[i] = -INFINITY; l[i] = 0.0f;
        #pragma unroll
        for (int j = 0; j < 4; j++) o[i][j] = 0.0f;
    }

    for (int kt = 0; kt < Nn / 128; kt++) {
        __syncthreads();
        const float* Kg = g_k + ((size_t)bh * Nn + kt * 128) * HDd;
        const float* Vg = g_v + ((size_t)bh * Nn + kt * 128) * HDd;
        #pragma unroll
        for (int i = 0; i < 32; i++) {
            int idx = tid + i * 256;
            int key = idx >> 6, d = idx & 63;
            Kt[d * KTS + key] = Kg[(size_t)key * HDd + d];
        }
        #pragma unroll
        for (int i = 0; i < 8; i++) {
            int idx = tid + i * 256;
            int row = idx >> 4, d4 = idx & 15;
            *(float4*)&Vs[row * VS_ + d4 * 4] = *(const float4*)(Vg + (size_t)row * HDd + d4 * 4);
        }
        __syncthreads();

        float s[8][8];
        #pragma unroll
        for (int i = 0; i < 8; i++)
            #pragma unroll
            for (int j = 0; j < 8; j++) s[i][j] = 0.0f;

        #pragma unroll 4
        for (int d = 0; d < HDd; d++) {
            float a[8];
            #pragma unroll
            for (int i = 0; i < 8; i++) a[i] = Qs[(r0 + i) * VS_ + d];
            float4 b0 = *(float4*)&Kt[d * KTS + c0s];
            float4 b1 = *(float4*)&Kt[d * KTS + c0s + 4];
            float b[8] = {b0.x, b0.y, b0.z, b0.w, b1.x, b1.y, b1.z, b1.w};
            #pragma unroll
            for (int i = 0; i < 8; i++)
                #pragma unroll
                for (int j = 0; j < 8; j++) s[i][j] += a[i] * b[j];
        }

        #pragma unroll
        for (int i = 0; i < 8; i++) {
            float mx = s[i][0];
            #pragma unroll
            for (int j = 1; j < 8; j++) mx = fmaxf(mx, s[i][j]);
            mx = fmaxf(mx, __shfl_xor_sync(0xffffffffu, mx, 1));
            mx = fmaxf(mx, __shfl_xor_sync(0xffffffffu, mx, 2));
            mx = fmaxf(mx, __shfl_xor_sync(0xffffffffu, mx, 4));
            mx = fmaxf(mx, __shfl_xor_sync(0xffffffffu, mx, 8));
            float mn   = fmaxf(m[i], mx);
            float corr = __expf(m[i] - mn);
            float sum  = 0.0f;
            #pragma unroll
            for (int j = 0; j < 8; j++) {
                s[i][j] = __expf(s[i][j] - mn);
                sum += s[i][j];
            }
            sum += __shfl_xor_sync(0xffffffffu, sum, 1);
            sum += __shfl_xor_sync(0xffffffffu, sum, 2);
            sum += __shfl_xor_sync(0xffffffffu, sum, 4);
            sum += __shfl_xor_sync(0xffffffffu, sum, 8);
            l[i] = l[i] * corr + sum;
            m[i] = mn;
            #pragma unroll
            for (int j = 0; j < 4; j++) o[i][j] *= corr;
        }

        #pragma unroll
        for (int i = 0; i < 8; i++) {
            *(float4*)&Ps[(r0 + i) * PS_ + c0s]     = make_float4(s[i][0], s[i][1], s[i][2], s[i][3]);
            *(float4*)&Ps[(r0 + i) * PS_ + c0s + 4] = make_float4(s[i][4], s[i][5], s[i][6], s[i][7]);
        }
        __syncthreads();

        #pragma unroll 4
        for (int k = 0; k < 128; k++) {
            float p[8];
            #pragma unroll
            for (int i = 0; i < 8; i++) p[i] = Ps[(r0 + i) * PS_ + k];
            float4 vv = *(float4*)&Vs[k * VS_ + c0d];
            float v[4] = {vv.x, vv.y, vv.z, vv.w};
            #pragma unroll
            for (int i = 0; i < 8; i++)
                #pragma unroll
                for (int j = 0; j < 4; j++) o[i][j] += p[i] * v[j];
        }
    }

    float* Og = g_o + ((size_t)bh * Nn + q0) * HDd;
    #pragma unroll
    for (int i = 0; i < 8; i++) {
        float inv = 1.0f / l[i];
        *(float4*)(Og + (size_t)(r0 + i) * HDd + c0d) =
            make_float4(o[i][0] * inv, o[i][1] * inv, o[i][2] * inv, o[i][3] * inv);
    }
}

// ---------------------------------------------------------------------------
extern "C" void kernel_launch(void* const* d_in, const int* in_sizes, int n_in,
                              void* d_out, int out_size) {
    const float* x      = (const float*)d_in[0];
    const float* w_qkv  = (const float*)d_in[1];
    const float* b_qkv  = (const float*)d_in[2];
    const float* gq     = (const float*)d_in[3];
    const float* beq    = (const float*)d_in[4];
    const float* gk     = (const float*)d_in[5];
    const float* bek    = (const float*)d_in[6];
    const float* w_proj = (const float*)d_in[7];
    const float* b_proj = (const float*)d_in[8];
    float* out = (float*)d_out;

    cudaFuncSetAttribute(attn_kernel, cudaFuncAttributeMaxDynamicSharedMemorySize, ATTN_SMEM);

    // 1) QKV GEMM (bf16 hi/lo wmma) + bias + scatter
    gemm_wmma<<<dim3(3 * Cc / 128, ROWS / 128), 256>>>(x, w_qkv, b_qkv, nullptr, 3 * Cc, 1);
    // 2) LN on Q (scaled) and K
    ln_kernel<<<(2 * Bb * Hh * Nn) / 8, 256>>>(gq, beq, gk, bek);
    // 3) flash attention (SIMT, proven)
    attn_kernel<<<dim3(Nn / 128, Bb * Hh), 256, ATTN_SMEM>>>();
    // 4) projection GEMM (bf16 hi/lo wmma), A gathered from g_o in staging
    gemm_wmma<<<dim3(Cc / 128, ROWS / 128), 256>>>(nullptr, w_proj, b_proj, out, Cc, 0);
}

// round 9
// speedup vs baseline: 3.4103x; 1.1394x over previous
#include <cuda_runtime.h>
#include <cuda_bf16.h>
#include <mma.h>
#include <math.h>

using namespace nvcuda;

#define Bb   2
#define Nn   2048
#define Cc   1024
#define Hh   16
#define HDd  64
#define ROWS (Bb * Nn)          // 4096
#define LNEPS 1e-5f

typedef __nv_bfloat16 bf16;

// Scratch (device globals; allocation is forbidden). All N-MAJOR [bh][n][d].
__device__ float g_q[Bb * Hh * Nn * HDd];
__device__ float g_k[Bb * Hh * Nn * HDd];
__device__ float g_v[Bb * Hh * Nn * HDd];
__device__ float g_o[Bb * Hh * Nn * HDd];

__device__ __forceinline__ void split_bf16(float f, bf16& hi, bf16& lo) {
    hi = __float2bfloat16(f);
    lo = __float2bfloat16(f - __bfloat162float(hi));
}

// ---------------------------------------------------------------------------
// bf16 hi/lo wmma GEMM (unchanged from R8, proven).
// ---------------------------------------------------------------------------
#define ALD 24
#define BLD 136
#define SLD 20

#define OFF_ASH 0
#define OFF_ASL 384
#define OFF_BSH 768
#define OFF_BSL 1040
#define OFF_ST  1312
#define POOL_SZ 1952

__global__ void gemm_wmma(const float* __restrict__ A,
                          const float* __restrict__ W,
                          const float* __restrict__ bias,
                          float* __restrict__ out,
                          int ldw, int mode) {
    __shared__ float4 pool[POOL_SZ];
    bf16*  Ash = (bf16*)(pool + OFF_ASH);
    bf16*  Asl = (bf16*)(pool + OFF_ASL);
    bf16*  Bsh = (bf16*)(pool + OFF_BSH);
    bf16*  Bsl = (bf16*)(pool + OFF_BSL);
    float* St  = (float*)(pool + OFF_ST);

    const int tid   = threadIdx.x;
    const int wid   = tid >> 5;
    const int lane  = tid & 31;
    const int warpM = wid >> 2;
    const int warpN = wid & 3;
    const int gr    = blockIdx.y * 128;
    const int gc    = blockIdx.x * 128;

    wmma::fragment<wmma::accumulator, 16, 16, 16, float> cf[4][2];
    #pragma unroll
    for (int mt = 0; mt < 4; mt++)
        #pragma unroll
        for (int nt = 0; nt < 2; nt++) wmma::fill_fragment(cf[mt][nt], 0.0f);

    for (int k0 = 0; k0 < Cc; k0 += 16) {
        if (mode) {
            #pragma unroll
            for (int p = 0; p < 2; p++) {
                int idx = tid + p * 256;
                int c4  = idx & 3;
                int mm  = idx >> 2;
                float4 v = *(const float4*)(A + (size_t)(gr + mm) * Cc + k0 + c4 * 4);
                bf16 h, l;
                split_bf16(v.x, h, l); Ash[mm * ALD + c4 * 4 + 0] = h; Asl[mm * ALD + c4 * 4 + 0] = l;
                split_bf16(v.y, h, l); Ash[mm * ALD + c4 * 4 + 1] = h; Asl[mm * ALD + c4 * 4 + 1] = l;
                split_bf16(v.z, h, l); Ash[mm * ALD + c4 * 4 + 2] = h; Asl[mm * ALD + c4 * 4 + 2] = l;
                split_bf16(v.w, h, l); Ash[mm * ALD + c4 * 4 + 3] = h; Asl[mm * ALD + c4 * 4 + 3] = l;
            }
        } else {
            #pragma unroll
            for (int i = 0; i < 8; i++) {
                int idx = tid + i * 256;
                int mm = idx >> 4, k = idx & 15;
                int row = gr + mm;
                int b = row / Nn, n = row % Nn;
                int kg = k0 + k;
                int h = kg >> 6, d = kg & 63;
                float v = g_o[((size_t)(b * Hh + h) * Nn + n) * HDd + d];
                bf16 hh, ll;
                split_bf16(v, hh, ll);
                Ash[mm * ALD + k] = hh;
                Asl[mm * ALD + k] = ll;
            }
        }
        #pragma unroll
        for (int p = 0; p < 2; p++) {
            int idx = tid + p * 256;
            int k  = idx >> 5;
            int n4 = idx & 31;
            float4 v = *(const float4*)(W + (size_t)(k0 + k) * ldw + gc + n4 * 4);
            bf16 h, l;
            split_bf16(v.x, h, l); Bsh[k * BLD + n4 * 4 + 0] = h; Bsl[k * BLD + n4 * 4 + 0] = l;
            split_bf16(v.y, h, l); Bsh[k * BLD + n4 * 4 + 1] = h; Bsl[k * BLD + n4 * 4 + 1] = l;
            split_bf16(v.z, h, l); Bsh[k * BLD + n4 * 4 + 2] = h; Bsl[k * BLD + n4 * 4 + 2] = l;
            split_bf16(v.w, h, l); Bsh[k * BLD + n4 * 4 + 3] = h; Bsl[k * BLD + n4 * 4 + 3] = l;
        }
        __syncthreads();

        wmma::fragment<wmma::matrix_a, 16, 16, 16, bf16, wmma::row_major> ah[4], al[4];
        wmma::fragment<wmma::matrix_b, 16, 16, 16, bf16, wmma::row_major> bh[2], bl[2];
        #pragma unroll
        for (int mt = 0; mt < 4; mt++) {
            wmma::load_matrix_sync(ah[mt], &Ash[(warpM * 64 + mt * 16) * ALD], ALD);
            wmma::load_matrix_sync(al[mt], &Asl[(warpM * 64 + mt * 16) * ALD], ALD);
        }
        #pragma unroll
        for (int nt = 0; nt < 2; nt++) {
            wmma::load_matrix_sync(bh[nt], &Bsh[warpN * 32 + nt * 16], BLD);
            wmma::load_matrix_sync(bl[nt], &Bsl[warpN * 32 + nt * 16], BLD);
        }
        #pragma unroll
        for (int mt = 0; mt < 4; mt++)
            #pragma unroll
            for (int nt = 0; nt < 2; nt++) {
                wmma::mma_sync(cf[mt][nt], ah[mt], bh[nt], cf[mt][nt]);
                wmma::mma_sync(cf[mt][nt], ah[mt], bl[nt], cf[mt][nt]);
                wmma::mma_sync(cf[mt][nt], al[mt], bh[nt], cf[mt][nt]);
            }
        __syncthreads();
    }

    float* stg = &St[wid * 16 * SLD];
    #pragma unroll
    for (int mt = 0; mt < 4; mt++) {
        #pragma unroll
        for (int nt = 0; nt < 2; nt++) {
            wmma::store_matrix_sync(stg, cf[mt][nt], SLD, wmma::mem_row_major);
            __syncwarp();
            #pragma unroll
            for (int i = 0; i < 8; i++) {
                int e = lane * 8 + i;
                int r = e >> 4, c = e & 15;
                int row = gr + warpM * 64 + mt * 16 + r;
                int col = gc + warpN * 32 + nt * 16 + c;
                float v = stg[r * SLD + c] + bias[col];
                if (mode) {
                    int b  = row / Nn, n = row % Nn;
                    int wh = col >> 10;
                    int ci = col & 1023;
                    int h  = ci >> 6, d = ci & 63;
                    size_t o = ((size_t)(b * Hh + h) * Nn + n) * HDd + d;
                    if (wh == 0)      g_q[o] = v;
                    else if (wh == 1) g_k[o] = v;
                    else              g_v[o] = v;
                } else {
                    out[(size_t)row * Cc + col] = v;
                }
            }
            __syncwarp();
        }
    }
}

// ---------------------------------------------------------------------------
// LayerNorm over HD=64, one warp per row (unchanged, proven).
// ---------------------------------------------------------------------------
__global__ void ln_kernel(const float* __restrict__ gq, const float* __restrict__ beq,
                          const float* __restrict__ gk, const float* __restrict__ bek) {
    const int R = Bb * Hh * Nn;
    int warp = (blockIdx.x * blockDim.x + threadIdx.x) >> 5;
    int lane = threadIdx.x & 31;
    if (warp >= 2 * R) return;

    bool isq = warp < R;
    float* buf       = isq ? g_q : g_k;
    const float* gam = isq ? gq  : gk;
    const float* bet = isq ? beq : bek;
    float scale      = isq ? 0.125f : 1.0f;
    int row = isq ? warp : warp - R;

    float v0 = buf[row * HDd + lane];
    float v1 = buf[row * HDd + 32 + lane];
    float s  = v0 + v1;
    float ss = v0 * v0 + v1 * v1;
    #pragma unroll
    for (int off = 16; off; off >>= 1) {
        s  += __shfl_xor_sync(0xffffffffu, s,  off);
        ss += __shfl_xor_sync(0xffffffffu, ss, off);
    }
    float mu  = s * (1.0f / HDd);
    float var = ss * (1.0f / HDd) - mu * mu;
    float inv = rsqrtf(var + LNEPS);
    buf[row * HDd + lane]      = ((v0 - mu) * inv * gam[lane]      + bet[lane])      * scale;
    buf[row * HDd + 32 + lane] = ((v1 - mu) * inv * gam[lane + 32] + bet[lane + 32]) * scale;
}

// ---------------------------------------------------------------------------
// Flash attention via wmma bf16 hi/lo. 256 threads (8 warps), Q-block 128,
// KV tiles 64. Warp w owns q rows [w*16, w*16+16).
// Smem offsets in floats; bf16 regions addressed via bf16* casts.
// ---------------------------------------------------------------------------
#define BQS 72    // bf16 tile stride (144 B)
#define FQS 68    // f32 tile stride (272 B)
// float-offsets of regions
#define O_QH 0
#define O_QL 4608      // 128*72/2
#define O_KH 9216
#define O_KL 11520     // + 64*72/2 = 2304
#define O_VH 13824
#define O_VL 16128
#define O_PH 18432
#define O_PL 23040
#define O_SS 27648
#define O_OS 36352     // + 128*68 = 8704
#define O_MR 45056
#define O_LR 45184
#define O_CR 45312
#define ATTN_FLOATS 45440
#define ATTN_SMEM (ATTN_FLOATS * 4)    // 181760 B

__global__ void attn_wmma() {
    extern __shared__ float sm[];
    bf16*  Qh = (bf16*)(sm + O_QH);
    bf16*  Ql = (bf16*)(sm + O_QL);
    bf16*  Kh = (bf16*)(sm + O_KH);
    bf16*  Kl = (bf16*)(sm + O_KL);
    bf16*  Vh = (bf16*)(sm + O_VH);
    bf16*  Vl = (bf16*)(sm + O_VL);
    bf16*  Ph = (bf16*)(sm + O_PH);
    bf16*  Pl = (bf16*)(sm + O_PL);
    float* Ss = sm + O_SS;
    float* Os = sm + O_OS;
    float* mrow = sm + O_MR;
    float* lrow = sm + O_LR;
    float* crow = sm + O_CR;

    const int tid  = threadIdx.x;
    const int w    = tid >> 5;
    const int lane = tid & 31;
    const int bh   = blockIdx.y;
    const int q0   = blockIdx.x * 128;

    // stage Q (hi/lo), zero Os, init m/l
    const float* Qg = g_q + ((size_t)bh * Nn + q0) * HDd;
    #pragma unroll
    for (int i = 0; i < 8; i++) {
        int idx = tid + i * 256;           // 0..2047 float4s
        int row = idx >> 4, d4 = idx & 15;
        float4 v = *(const float4*)(Qg + (size_t)row * HDd + d4 * 4);
        bf16 h, l;
        split_bf16(v.x, h, l); Qh[row * BQS + d4 * 4 + 0] = h; Ql[row * BQS + d4 * 4 + 0] = l;
        split_bf16(v.y, h, l); Qh[row * BQS + d4 * 4 + 1] = h; Ql[row * BQS + d4 * 4 + 1] = l;
        split_bf16(v.z, h, l); Qh[row * BQS + d4 * 4 + 2] = h; Ql[row * BQS + d4 * 4 + 2] = l;
        split_bf16(v.w, h, l); Qh[row * BQS + d4 * 4 + 3] = h; Ql[row * BQS + d4 * 4 + 3] = l;
    }
    for (int i = tid; i < 128 * FQS; i += 256) Os[i] = 0.0f;
    if (tid < 128) { mrow[tid] = -INFINITY; lrow[tid] = 0.0f; }

    const int myrow = w * 16 + (lane >> 1);    // softmax row owned by this lane
    const int half  = lane & 1;                // 0: keys 0..31, 1: keys 32..63

    for (int kt = 0; kt < Nn / 64; kt++) {
        __syncthreads();   // protect Kh/Vh tiles from previous iteration readers
        const float* Kg = g_k + ((size_t)bh * Nn + kt * 64) * HDd;
        const float* Vg = g_v + ((size_t)bh * Nn + kt * 64) * HDd;
        #pragma unroll
        for (int i = 0; i < 4; i++) {
            int idx = tid + i * 256;       // 0..1023 float4s
            int row = idx >> 4, d4 = idx & 15;
            float4 kv = *(const float4*)(Kg + (size_t)row * HDd + d4 * 4);
            float4 vv = *(const float4*)(Vg + (size_t)row * HDd + d4 * 4);
            bf16 h, l;
            split_bf16(kv.x, h, l); Kh[row * BQS + d4 * 4 + 0] = h; Kl[row * BQS + d4 * 4 + 0] = l;
            split_bf16(kv.y, h, l); Kh[row * BQS + d4 * 4 + 1] = h; Kl[row * BQS + d4 * 4 + 1] = l;
            split_bf16(kv.z, h, l); Kh[row * BQS + d4 * 4 + 2] = h; Kl[row * BQS + d4 * 4 + 2] = l;
            split_bf16(kv.w, h, l); Kh[row * BQS + d4 * 4 + 3] = h; Kl[row * BQS + d4 * 4 + 3] = l;
            split_bf16(vv.x, h, l); Vh[row * BQS + d4 * 4 + 0] = h; Vl[row * BQS + d4 * 4 + 0] = l;
            split_bf16(vv.y, h, l); Vh[row * BQS + d4 * 4 + 1] = h; Vl[row * BQS + d4 * 4 + 1] = l;
            split_bf16(vv.z, h, l); Vh[row * BQS + d4 * 4 + 2] = h; Vl[row * BQS + d4 * 4 + 2] = l;
            split_bf16(vv.w, h, l); Vh[row * BQS + d4 * 4 + 3] = h; Vl[row * BQS + d4 * 4 + 3] = l;
        }
        __syncthreads();

        // ---- S = Q . K^T : warp computes its 16 rows x 64 keys ----
        {
            wmma::fragment<wmma::accumulator, 16, 16, 16, float> sf[4];
            #pragma unroll
            for (int nt = 0; nt < 4; nt++) wmma::fill_fragment(sf[nt], 0.0f);
            #pragma unroll
            for (int ks = 0; ks < 4; ks++) {
                wmma::fragment<wmma::matrix_a, 16, 16, 16, bf16, wmma::row_major> ah, al;
                wmma::load_matrix_sync(ah, &Qh[(w * 16) * BQS + ks * 16], BQS);
                wmma::load_matrix_sync(al, &Ql[(w * 16) * BQS + ks * 16], BQS);
                #pragma unroll
                for (int nt = 0; nt < 4; nt++) {
                    wmma::fragment<wmma::matrix_b, 16, 16, 16, bf16, wmma::col_major> bhf, blf;
                    wmma::load_matrix_sync(bhf, &Kh[(nt * 16) * BQS + ks * 16], BQS);
                    wmma::load_matrix_sync(blf, &Kl[(nt * 16) * BQS + ks * 16], BQS);
                    wmma::mma_sync(sf[nt], ah, bhf, sf[nt]);
                    wmma::mma_sync(sf[nt], ah, blf, sf[nt]);
                    wmma::mma_sync(sf[nt], al, bhf, sf[nt]);
                }
            }
            #pragma unroll
            for (int nt = 0; nt < 4; nt++)
                wmma::store_matrix_sync(&Ss[(w * 16) * FQS + nt * 16], sf[nt], FQS, wmma::mem_row_major);
            __syncwarp();
        }

        // ---- online softmax on this warp's 16 rows ----
        {
            float* srow = &Ss[myrow * FQS + half * 32];
            float sv[32];
            float mx = -INFINITY;
            #pragma unroll
            for (int j = 0; j < 32; j++) { sv[j] = srow[j]; mx = fmaxf(mx, sv[j]); }
            mx = fmaxf(mx, __shfl_xor_sync(0xffffffffu, mx, 1));
            float mold = mrow[myrow];
            float mnew = fmaxf(mold, mx);
            float corr = __expf(mold - mnew);
            float sum = 0.0f;
            #pragma unroll
            for (int j = 0; j < 32; j++) {
                float e = __expf(sv[j] - mnew);
                sum += e;
                bf16 h, l;
                split_bf16(e, h, l);
                Ph[myrow * BQS + half * 32 + j] = h;
                Pl[myrow * BQS + half * 32 + j] = l;
            }
            sum += __shfl_xor_sync(0xffffffffu, sum, 1);
            if (half == 0) {
                lrow[myrow] = lrow[myrow] * corr + sum;
                mrow[myrow] = mnew;
                crow[myrow] = corr;
            }
            __syncwarp();
        }

        // ---- PV = P . V : 16 rows x 64 d, k over 64 keys (staged into Ss) ----
        {
            wmma::fragment<wmma::accumulator, 16, 16, 16, float> pvf[4];
            #pragma unroll
            for (int nt = 0; nt < 4; nt++) wmma::fill_fragment(pvf[nt], 0.0f);
            #pragma unroll
            for (int ks = 0; ks < 4; ks++) {
                wmma::fragment<wmma::matrix_a, 16, 16, 16, bf16, wmma::row_major> ah, al;
                wmma::load_matrix_sync(ah, &Ph[(w * 16) * BQS + ks * 16], BQS);
                wmma::load_matrix_sync(al, &Pl[(w * 16) * BQS + ks * 16], BQS);
                #pragma unroll
                for (int nt = 0; nt < 4; nt++) {
                    wmma::fragment<wmma::matrix_b, 16, 16, 16, bf16, wmma::row_major> bhf, blf;
                    wmma::load_matrix_sync(bhf, &Vh[(ks * 16) * BQS + nt * 16], BQS);
                    wmma::load_matrix_sync(blf, &Vl[(ks * 16) * BQS + nt * 16], BQS);
                    wmma::mma_sync(pvf[nt], ah, bhf, pvf[nt]);
                    wmma::mma_sync(pvf[nt], ah, blf, pvf[nt]);
                    wmma::mma_sync(pvf[nt], al, bhf, pvf[nt]);
                }
            }
            #pragma unroll
            for (int nt = 0; nt < 4; nt++)
                wmma::store_matrix_sync(&Ss[(w * 16) * FQS + nt * 16], pvf[nt], FQS, wmma::mem_row_major);
            __syncwarp();
        }

        // ---- O = O * corr + PV  (warp-private 16x64 band) ----
        #pragma unroll
        for (int i = 0; i < 32; i++) {
            int e = lane + 32 * i;        // 0..1023
            int r = e >> 6, c = e & 63;
            int gr_ = w * 16 + r;
            Os[gr_ * FQS + c] = Os[gr_ * FQS + c] * crow[gr_] + Ss[gr_ * FQS + c];
        }
    }

    __syncthreads();
    // normalize + write O (n-major)
    float* Og = g_o + ((size_t)bh * Nn + q0) * HDd;
    for (int i = 0; i < 32; i++) {
        int idx = tid + i * 256;          // 0..8191
        int row = idx >> 6, d = idx & 63;
        Og[(size_t)row * HDd + d] = Os[row * FQS + d] / lrow[row];
    }
}

// ---------------------------------------------------------------------------
extern "C" void kernel_launch(void* const* d_in, const int* in_sizes, int n_in,
                              void* d_out, int out_size) {
    const float* x      = (const float*)d_in[0];
    const float* w_qkv  = (const float*)d_in[1];
    const float* b_qkv  = (const float*)d_in[2];
    const float* gq     = (const float*)d_in[3];
    const float* beq    = (const float*)d_in[4];
    const float* gk     = (const float*)d_in[5];
    const float* bek    = (const float*)d_in[6];
    const float* w_proj = (const float*)d_in[7];
    const float* b_proj = (const float*)d_in[8];
    float* out = (float*)d_out;

    cudaFuncSetAttribute(attn_wmma, cudaFuncAttributeMaxDynamicSharedMemorySize, ATTN_SMEM);

    // 1) QKV GEMM (bf16 hi/lo wmma) + bias + scatter
    gemm_wmma<<<dim3(3 * Cc / 128, ROWS / 128), 256>>>(x, w_qkv, b_qkv, nullptr, 3 * Cc, 1);
    // 2) LN on Q (scaled) and K
    ln_kernel<<<(2 * Bb * Hh * Nn) / 8, 256>>>(gq, beq, gk, bek);
    // 3) flash attention (wmma bf16 hi/lo)
    attn_wmma<<<dim3(Nn / 128, Bb * Hh), 256, ATTN_SMEM>>>();
    // 4) projection GEMM (bf16 hi/lo wmma), A gathered from g_o in staging
    gemm_wmma<<<dim3(Cc / 128, ROWS / 128), 256>>>(nullptr, w_proj, b_proj, out, Cc, 0);
}

// round 11
// speedup vs baseline: 3.9890x; 1.1697x over previous
#include <cuda_runtime.h>
#include <cuda_bf16.h>
#include <mma.h>
#include <math.h>

using namespace nvcuda;

#define Bb   2
#define Nn   2048
#define Cc   1024
#define Hh   16
#define HDd  64
#define ROWS (Bb * Nn)          // 4096
#define LNEPS 1e-5f

typedef __nv_bfloat16 bf16;

// f32 scratch (QKV GEMM output for Q/K; LN reads these)
__device__ float g_q[Bb * Hh * Nn * HDd];
__device__ float g_k[Bb * Hh * Nn * HDd];

// bf16 hi/lo scratch as float4 arrays (16B aligned by type), cast to bf16* in device code.
// NOTE: these symbols are ONLY referenced from device code — never passed from host.
__device__ float4 g_xh4[524288],  g_xl4[524288];    // x        [4096][1024]
__device__ float4 g_wqh4[393216], g_wql4[393216];   // w_qkv    [1024][3072]
__device__ float4 g_wph4[131072], g_wpl4[131072];   // w_proj   [1024][1024]
__device__ float4 g_qh4[524288],  g_ql4[524288];    // Q (post-LN)  [bh][n][d]
__device__ float4 g_kh4[524288],  g_kl4[524288];    // K (post-LN)  [bh][n][d]
__device__ float4 g_vh4[524288],  g_vl4[524288];    // V            [bh][n][d]
__device__ float4 g_oh4[524288],  g_ol4[524288];    // attn out, row-major [4096][1024]

__device__ __forceinline__ void split_bf16(float f, bf16& hi, bf16& lo) {
    hi = __float2bfloat16(f);
    lo = __float2bfloat16(f - __bfloat162float(hi));
}

// ---------------------------------------------------------------------------
// conv: f32 -> bf16 hi/lo, 8 elements per thread. which: 0=x, 1=w_qkv, 2=w_proj
// ---------------------------------------------------------------------------
__global__ void conv_kernel(const float* src, int which) {
    float4* dh4 = (which == 0) ? g_xh4 : (which == 1) ? g_wqh4 : g_wph4;
    float4* dl4 = (which == 0) ? g_xl4 : (which == 1) ? g_wql4 : g_wpl4;
    int i = blockIdx.x * blockDim.x + threadIdx.x;      // one float4-pair (8 floats)
    float4 a = *(const float4*)(src + (size_t)i * 8);
    float4 b = *(const float4*)(src + (size_t)i * 8 + 4);
    float v[8] = {a.x, a.y, a.z, a.w, b.x, b.y, b.z, b.w};
    __nv_bfloat162* dh = (__nv_bfloat162*)(dh4 + i);
    __nv_bfloat162* dl = (__nv_bfloat162*)(dl4 + i);
    #pragma unroll
    for (int p = 0; p < 4; p++) {
        bf16 h0, l0, h1, l1;
        split_bf16(v[2 * p], h0, l0);
        split_bf16(v[2 * p + 1], h1, l1);
        __nv_bfloat162 hh; hh.x = h0; hh.y = h1;
        __nv_bfloat162 ll; ll.x = l0; ll.y = l1;
        dh[p] = hh;
        dl[p] = ll;
    }
}

// ---------------------------------------------------------------------------
// bf16 hi/lo wmma GEMM, pre-converted operands, BK=32, copy-only staging.
// 128x128 tile, 256 threads, 8 warps (2x4), warp tile 64x32.
// mode=1: A=g_x, W=g_wq (ldw 3072); epilogue scatters Q/K (f32) + V (hi/lo).
// mode=0: A=g_o,  W=g_wp (ldw 1024); epilogue writes out + bias.
// ---------------------------------------------------------------------------
#define AS2 40     // A smem stride (bf16), mult of 8
#define BS2 136    // B smem stride (bf16), mult of 8
#define SLD 20     // f32 staging stride

#define OFF_ASH 0
#define OFF_ASL 640
#define OFF_BSH 1280
#define OFF_BSL 1824
#define OFF_ST  2368
#define POOL_SZ 3008

__global__ void gemm_wmma(const float* bias, float* out, int mode) {
    __shared__ float4 pool[POOL_SZ];
    bf16*  Ash = (bf16*)(pool + OFF_ASH);
    bf16*  Asl = (bf16*)(pool + OFF_ASL);
    bf16*  Bsh = (bf16*)(pool + OFF_BSH);
    bf16*  Bsl = (bf16*)(pool + OFF_BSL);
    float* St  = (float*)(pool + OFF_ST);

    const bf16* Ah = (const bf16*)(mode ? g_xh4 : g_oh4);
    const bf16* Al = (const bf16*)(mode ? g_xl4 : g_ol4);
    const bf16* Wh = (const bf16*)(mode ? g_wqh4 : g_wph4);
    const bf16* Wl = (const bf16*)(mode ? g_wql4 : g_wpl4);
    const int ldw  = mode ? 3 * Cc : Cc;

    const int tid   = threadIdx.x;
    const int wid   = tid >> 5;
    const int lane  = tid & 31;
    const int warpM = wid >> 2;
    const int warpN = wid & 3;
    const int gr    = blockIdx.y * 128;
    const int gc    = blockIdx.x * 128;

    wmma::fragment<wmma::accumulator, 16, 16, 16, float> cf[4][2];
    #pragma unroll
    for (int mt = 0; mt < 4; mt++)
        #pragma unroll
        for (int nt = 0; nt < 2; nt++) wmma::fill_fragment(cf[mt][nt], 0.0f);

    for (int k0 = 0; k0 < Cc; k0 += 32) {
        // A tiles 128x32 (hi+lo): 512 uint4 each, 2 per thread
        #pragma unroll
        for (int p = 0; p < 2; p++) {
            int idx = tid + p * 256;
            int row = idx >> 2, c4 = idx & 3;
            size_t src = (size_t)(gr + row) * Cc + k0 + c4 * 8;
            *(uint4*)&Ash[row * AS2 + c4 * 8] = *(const uint4*)(Ah + src);
            *(uint4*)&Asl[row * AS2 + c4 * 8] = *(const uint4*)(Al + src);
        }
        // B tiles 32x128 (hi+lo): 512 uint4 each, 2 per thread
        #pragma unroll
        for (int p = 0; p < 2; p++) {
            int idx = tid + p * 256;
            int k = idx >> 4, n4 = idx & 15;
            size_t src = (size_t)(k0 + k) * ldw + gc + n4 * 8;
            *(uint4*)&Bsh[k * BS2 + n4 * 8] = *(const uint4*)(Wh + src);
            *(uint4*)&Bsl[k * BS2 + n4 * 8] = *(const uint4*)(Wl + src);
        }
        __syncthreads();

        #pragma unroll
        for (int ks = 0; ks < 2; ks++) {
            wmma::fragment<wmma::matrix_a, 16, 16, 16, bf16, wmma::row_major> ah[4], al[4];
            wmma::fragment<wmma::matrix_b, 16, 16, 16, bf16, wmma::row_major> bh[2], bl[2];
            #pragma unroll
            for (int mt = 0; mt < 4; mt++) {
                wmma::load_matrix_sync(ah[mt], &Ash[(warpM * 64 + mt * 16) * AS2 + ks * 16], AS2);
                wmma::load_matrix_sync(al[mt], &Asl[(warpM * 64 + mt * 16) * AS2 + ks * 16], AS2);
            }
            #pragma unroll
            for (int nt = 0; nt < 2; nt++) {
                wmma::load_matrix_sync(bh[nt], &Bsh[(ks * 16) * BS2 + warpN * 32 + nt * 16], BS2);
                wmma::load_matrix_sync(bl[nt], &Bsl[(ks * 16) * BS2 + warpN * 32 + nt * 16], BS2);
            }
            #pragma unroll
            for (int mt = 0; mt < 4; mt++)
                #pragma unroll
                for (int nt = 0; nt < 2; nt++) {
                    wmma::mma_sync(cf[mt][nt], ah[mt], bh[nt], cf[mt][nt]);
                    wmma::mma_sync(cf[mt][nt], ah[mt], bl[nt], cf[mt][nt]);
                    wmma::mma_sync(cf[mt][nt], al[mt], bh[nt], cf[mt][nt]);
                }
        }
        __syncthreads();
    }

    bf16* vhE = (bf16*)g_vh4;
    bf16* vlE = (bf16*)g_vl4;
    float* stg = &St[wid * 16 * SLD];
    #pragma unroll
    for (int mt = 0; mt < 4; mt++) {
        #pragma unroll
        for (int nt = 0; nt < 2; nt++) {
            wmma::store_matrix_sync(stg, cf[mt][nt], SLD, wmma::mem_row_major);
            __syncwarp();
            #pragma unroll
            for (int i = 0; i < 8; i++) {
                int e = lane * 8 + i;
                int r = e >> 4, c = e & 15;
                int row = gr + warpM * 64 + mt * 16 + r;
                int col = gc + warpN * 32 + nt * 16 + c;
                float v = stg[r * SLD + c] + bias[col];
                if (mode) {
                    int b  = row / Nn, n = row % Nn;
                    int wh = col >> 10;
                    int ci = col & 1023;
                    int h  = ci >> 6, d = ci & 63;
                    size_t o = ((size_t)(b * Hh + h) * Nn + n) * HDd + d;
                    if (wh == 0)      g_q[o] = v;
                    else if (wh == 1) g_k[o] = v;
                    else {
                        bf16 hh, ll;
                        split_bf16(v, hh, ll);
                        vhE[o] = hh;
                        vlE[o] = ll;
                    }
                } else {
                    out[(size_t)row * Cc + col] = v;
                }
            }
            __syncwarp();
        }
    }
}

// ---------------------------------------------------------------------------
// LayerNorm over HD=64, one warp per row; emits bf16 hi/lo (Q scaled).
// ---------------------------------------------------------------------------
__global__ void ln_kernel(const float* __restrict__ gq, const float* __restrict__ beq,
                          const float* __restrict__ gk, const float* __restrict__ bek) {
    const int R = Bb * Hh * Nn;
    int warp = (blockIdx.x * blockDim.x + threadIdx.x) >> 5;
    int lane = threadIdx.x & 31;
    if (warp >= 2 * R) return;

    bool isq = warp < R;
    const float* buf = isq ? g_q : g_k;
    bf16* outh = (bf16*)(isq ? g_qh4 : g_kh4);
    bf16* outl = (bf16*)(isq ? g_ql4 : g_kl4);
    const float* gam = isq ? gq  : gk;
    const float* bet = isq ? beq : bek;
    float scale      = isq ? 0.125f : 1.0f;
    int row = isq ? warp : warp - R;

    float v0 = buf[(size_t)row * HDd + lane];
    float v1 = buf[(size_t)row * HDd + 32 + lane];
    float s  = v0 + v1;
    float ss = v0 * v0 + v1 * v1;
    #pragma unroll
    for (int off = 16; off; off >>= 1) {
        s  += __shfl_xor_sync(0xffffffffu, s,  off);
        ss += __shfl_xor_sync(0xffffffffu, ss, off);
    }
    float mu  = s * (1.0f / HDd);
    float var = ss * (1.0f / HDd) - mu * mu;
    float inv = rsqrtf(var + LNEPS);
    float r0 = ((v0 - mu) * inv * gam[lane]      + bet[lane])      * scale;
    float r1 = ((v1 - mu) * inv * gam[lane + 32] + bet[lane + 32]) * scale;
    bf16 h, l;
    split_bf16(r0, h, l);
    outh[(size_t)row * HDd + lane] = h;
    outl[(size_t)row * HDd + lane] = l;
    split_bf16(r1, h, l);
    outh[(size_t)row * HDd + 32 + lane] = h;
    outl[(size_t)row * HDd + 32 + lane] = l;
}

// ---------------------------------------------------------------------------
// Flash attention via wmma bf16 hi/lo; copy-only staging from pre-split Q/K/V.
// 256 threads (8 warps), Q-block 128, KV tiles 64.
// ---------------------------------------------------------------------------
#define BQS 72    // bf16 tile stride
#define FQS 68    // f32 tile stride
#define O_QH 0
#define O_QL 4608
#define O_KH 9216
#define O_KL 11520
#define O_VH 13824
#define O_VL 16128
#define O_PH 18432
#define O_PL 23040
#define O_SS 27648
#define O_OS 36352
#define O_MR 45056
#define O_LR 45184
#define O_CR 45312
#define ATTN_FLOATS 45440
#define ATTN_SMEM (ATTN_FLOATS * 4)    // 181760 B

__global__ void attn_wmma() {
    extern __shared__ float sm[];
    bf16*  Qh = (bf16*)(sm + O_QH);
    bf16*  Ql = (bf16*)(sm + O_QL);
    bf16*  Kh = (bf16*)(sm + O_KH);
    bf16*  Kl = (bf16*)(sm + O_KL);
    bf16*  Vh = (bf16*)(sm + O_VH);
    bf16*  Vl = (bf16*)(sm + O_VL);
    bf16*  Ph = (bf16*)(sm + O_PH);
    bf16*  Pl = (bf16*)(sm + O_PL);
    float* Ss = sm + O_SS;
    float* Os = sm + O_OS;
    float* mrow = sm + O_MR;
    float* lrow = sm + O_LR;
    float* crow = sm + O_CR;

    const int tid  = threadIdx.x;
    const int w    = tid >> 5;
    const int lane = tid & 31;
    const int bh   = blockIdx.y;
    const int q0   = blockIdx.x * 128;

    // stage Q (copy, 1024 uint4 per half)
    const bf16* QhG = (const bf16*)g_qh4 + ((size_t)bh * Nn + q0) * HDd;
    const bf16* QlG = (const bf16*)g_ql4 + ((size_t)bh * Nn + q0) * HDd;
    #pragma unroll
    for (int i = 0; i < 4; i++) {
        int idx = tid + i * 256;          // 0..1023
        int row = idx >> 3, c8 = idx & 7;
        *(uint4*)&Qh[row * BQS + c8 * 8] = *(const uint4*)(QhG + (size_t)row * HDd + c8 * 8);
        *(uint4*)&Ql[row * BQS + c8 * 8] = *(const uint4*)(QlG + (size_t)row * HDd + c8 * 8);
    }
    for (int i = tid; i < 128 * FQS; i += 256) Os[i] = 0.0f;
    if (tid < 128) { mrow[tid] = -INFINITY; lrow[tid] = 0.0f; }

    const int myrow = w * 16 + (lane >> 1);
    const int half  = lane & 1;

    for (int kt = 0; kt < Nn / 64; kt++) {
        __syncthreads();
        const bf16* KhG = (const bf16*)g_kh4 + ((size_t)bh * Nn + kt * 64) * HDd;
        const bf16* KlG = (const bf16*)g_kl4 + ((size_t)bh * Nn + kt * 64) * HDd;
        const bf16* VhG = (const bf16*)g_vh4 + ((size_t)bh * Nn + kt * 64) * HDd;
        const bf16* VlG = (const bf16*)g_vl4 + ((size_t)bh * Nn + kt * 64) * HDd;
        #pragma unroll
        for (int i = 0; i < 2; i++) {
            int idx = tid + i * 256;      // 0..511
            int row = idx >> 3, c8 = idx & 7;
            size_t src = (size_t)row * HDd + c8 * 8;
            *(uint4*)&Kh[row * BQS + c8 * 8] = *(const uint4*)(KhG + src);
            *(uint4*)&Kl[row * BQS + c8 * 8] = *(const uint4*)(KlG + src);
            *(uint4*)&Vh[row * BQS + c8 * 8] = *(const uint4*)(VhG + src);
            *(uint4*)&Vl[row * BQS + c8 * 8] = *(const uint4*)(VlG + src);
        }
        __syncthreads();

        // ---- S = Q . K^T ----
        {
            wmma::fragment<wmma::accumulator, 16, 16, 16, float> sf[4];
            #pragma unroll
            for (int nt = 0; nt < 4; nt++) wmma::fill_fragment(sf[nt], 0.0f);
            #pragma unroll
            for (int ks = 0; ks < 4; ks++) {
                wmma::fragment<wmma::matrix_a, 16, 16, 16, bf16, wmma::row_major> ah, al;
                wmma::load_matrix_sync(ah, &Qh[(w * 16) * BQS + ks * 16], BQS);
                wmma::load_matrix_sync(al, &Ql[(w * 16) * BQS + ks * 16], BQS);
                #pragma unroll
                for (int nt = 0; nt < 4; nt++) {
                    wmma::fragment<wmma::matrix_b, 16, 16, 16, bf16, wmma::col_major> bhf, blf;
                    wmma::load_matrix_sync(bhf, &Kh[(nt * 16) * BQS + ks * 16], BQS);
                    wmma::load_matrix_sync(blf, &Kl[(nt * 16) * BQS + ks * 16], BQS);
                    wmma::mma_sync(sf[nt], ah, bhf, sf[nt]);
                    wmma::mma_sync(sf[nt], ah, blf, sf[nt]);
                    wmma::mma_sync(sf[nt], al, bhf, sf[nt]);
                }
            }
            #pragma unroll
            for (int nt = 0; nt < 4; nt++)
                wmma::store_matrix_sync(&Ss[(w * 16) * FQS + nt * 16], sf[nt], FQS, wmma::mem_row_major);
            __syncwarp();
        }

        // ---- online softmax on this warp's 16 rows ----
        {
            float* srow = &Ss[myrow * FQS + half * 32];
            float sv[32];
            float mx = -INFINITY;
            #pragma unroll
            for (int j = 0; j < 32; j++) { sv[j] = srow[j]; mx = fmaxf(mx, sv[j]); }
            mx = fmaxf(mx, __shfl_xor_sync(0xffffffffu, mx, 1));
            float mold = mrow[myrow];
            float mnew = fmaxf(mold, mx);
            float corr = __expf(mold - mnew);
            float sum = 0.0f;
            #pragma unroll
            for (int j = 0; j < 32; j++) {
                float e = __expf(sv[j] - mnew);
                sum += e;
                bf16 h, l;
                split_bf16(e, h, l);
                Ph[myrow * BQS + half * 32 + j] = h;
                Pl[myrow * BQS + half * 32 + j] = l;
            }
            sum += __shfl_xor_sync(0xffffffffu, sum, 1);
            if (half == 0) {
                lrow[myrow] = lrow[myrow] * corr + sum;
                mrow[myrow] = mnew;
                crow[myrow] = corr;
            }
            __syncwarp();
        }

        // ---- PV = P . V ----
        {
            wmma::fragment<wmma::accumulator, 16, 16, 16, float> pvf[4];
            #pragma unroll
            for (int nt = 0; nt < 4; nt++) wmma::fill_fragment(pvf[nt], 0.0f);
            #pragma unroll
            for (int ks = 0; ks < 4; ks++) {
                wmma::fragment<wmma::matrix_a, 16, 16, 16, bf16, wmma::row_major> ah, al;
                wmma::load_matrix_sync(ah, &Ph[(w * 16) * BQS + ks * 16], BQS);
                wmma::load_matrix_sync(al, &Pl[(w * 16) * BQS + ks * 16], BQS);
                #pragma unroll
                for (int nt = 0; nt < 4; nt++) {
                    wmma::fragment<wmma::matrix_b, 16, 16, 16, bf16, wmma::row_major> bhf, blf;
                    wmma::load_matrix_sync(bhf, &Vh[(ks * 16) * BQS + nt * 16], BQS);
                    wmma::load_matrix_sync(blf, &Vl[(ks * 16) * BQS + nt * 16], BQS);
                    wmma::mma_sync(pvf[nt], ah, bhf, pvf[nt]);
                    wmma::mma_sync(pvf[nt], ah, blf, pvf[nt]);
                    wmma::mma_sync(pvf[nt], al, bhf, pvf[nt]);
                }
            }
            #pragma unroll
            for (int nt = 0; nt < 4; nt++)
                wmma::store_matrix_sync(&Ss[(w * 16) * FQS + nt * 16], pvf[nt], FQS, wmma::mem_row_major);
            __syncwarp();
        }

        // ---- O = O * corr + PV ----
        #pragma unroll
        for (int i = 0; i < 32; i++) {
            int e = lane + 32 * i;
            int r = e >> 6, c = e & 63;
            int gr_ = w * 16 + r;
            Os[gr_ * FQS + c] = Os[gr_ * FQS + c] * crow[gr_] + Ss[gr_ * FQS + c];
        }
    }

    __syncthreads();
    // normalize + write O as bf16 hi/lo in proj-ready row-major [4096][1024]
    {
        int b = bh >> 4, h = bh & 15;     // bh = b*Hh + h
        bf16* ohE = (bf16*)g_oh4;
        bf16* olE = (bf16*)g_ol4;
        for (int i = 0; i < 32; i++) {
            int idx = tid + i * 256;       // 0..8191
            int row = idx >> 6, d = idx & 63;
            float v = Os[row * FQS + d] / lrow[row];
            size_t o = (size_t)(b * Nn + q0 + row) * Cc + h * HDd + d;
            bf16 hh, ll;
            split_bf16(v, hh, ll);
            ohE[o] = hh;
            olE[o] = ll;
        }
    }
}

// ---------------------------------------------------------------------------
extern "C" void kernel_launch(void* const* d_in, const int* in_sizes, int n_in,
                              void* d_out, int out_size) {
    const float* x      = (const float*)d_in[0];
    const float* w_qkv  = (const float*)d_in[1];
    const float* b_qkv  = (const float*)d_in[2];
    const float* gq     = (const float*)d_in[3];
    const float* beq    = (const float*)d_in[4];
    const float* gk     = (const float*)d_in[5];
    const float* bek    = (const float*)d_in[6];
    const float* w_proj = (const float*)d_in[7];
    const float* b_proj = (const float*)d_in[8];
    float* out = (float*)d_out;

    cudaFuncSetAttribute(attn_wmma, cudaFuncAttributeMaxDynamicSharedMemorySize, ATTN_SMEM);

    // 0) pre-convert inputs to bf16 hi/lo (destinations selected in device code)
    conv_kernel<<<2048, 256>>>(x,      0);
    conv_kernel<<<1536, 256>>>(w_qkv,  1);
    conv_kernel<<<512,  256>>>(w_proj, 2);
    // 1) QKV GEMM + bias; Q/K -> f32, V -> bf16 hi/lo
    gemm_wmma<<<dim3(3 * Cc / 128, ROWS / 128), 256>>>(b_qkv, nullptr, 1);
    // 2) LN on Q (scaled) and K -> bf16 hi/lo
    ln_kernel<<<(2 * Bb * Hh * Nn) / 8, 256>>>(gq, beq, gk, bek);
    // 3) flash attention -> O bf16 hi/lo (row-major)
    attn_wmma<<<dim3(Nn / 128, Bb * Hh), 256, ATTN_SMEM>>>();
    // 4) projection GEMM
    gemm_wmma<<<dim3(Cc / 128, ROWS / 128), 256>>>(b_proj, out, 0);
}